// round 8
// baseline (speedup 1.0000x reference)
#include <cuda_runtime.h>
#include <math.h>

#define GX 200
#define GY 200
#define GZ 20
#define NVOX (GX*GY*GZ)               // 800000
#define NCH 8
#define TOTAL_OUT (NVOX * (1 + NCH))  // 7,200,000 floats
#define N4 (TOTAL_OUT / 4)            // 1,800,000 float4

// Vector float4 reduction to global memory (sm_90+ PTX).
__device__ __forceinline__ void red_add_v4(float* addr, float a, float b, float c, float d) {
    asm volatile("red.global.add.v4.f32 [%0], {%1,%2,%3,%4};"
                 :: "l"(addr), "f"(a), "f"(b), "f"(c), "f"(d) : "memory");
}

// Full-chip grid-stride zero fill: coalesced STG.128, enough warps to
// saturate the L2 write path (R1's version was launch-config limited).
__global__ __launch_bounds__(256) void zero_kernel(float4* __restrict__ out) {
    int stride = gridDim.x * blockDim.x;
    float4 z = make_float4(0.f, 0.f, 0.f, 0.f);
    for (int i = blockIdx.x * blockDim.x + threadIdx.x; i < N4; i += stride)
        out[i] = z;
}

// One warp per Gaussian (reverted from 2-per-warp: E[max] of two ragged
// trip counts beat the tail-waste saving).
__global__ __launch_bounds__(256) void vox_kernel(
    const float* __restrict__ means, const float* __restrict__ opac,
    const float* __restrict__ scales, const float* __restrict__ rots,
    const float* __restrict__ feats,
    float* __restrict__ density, float* __restrict__ gfeat, int N)
{
    int g    = (blockIdx.x * blockDim.x + threadIdx.x) >> 5;
    int lane = threadIdx.x & 31;
    if (g >= N) return;

    // ---- per-Gaussian setup (redundant across lanes; broadcast loads) ----
    float mx = means[3*g+0], my = means[3*g+1], mz = means[3*g+2];
    float op = opac[g];
    float sx = scales[3*g+0], sy = scales[3*g+1], sz = scales[3*g+2];
    float qr = rots[4*g+0], qx = rots[4*g+1], qy = rots[4*g+2], qz = rots[4*g+3];

    float qn = rsqrtf(qr*qr + qx*qx + qy*qy + qz*qz + 1e-8f);
    qr *= qn; qx *= qn; qy *= qn; qz *= qn;

    float r00 = 1.f - 2.f*(qy*qy + qz*qz), r01 = 2.f*(qx*qy - qr*qz), r02 = 2.f*(qx*qz + qr*qy);
    float r10 = 2.f*(qx*qy + qr*qz), r11 = 1.f - 2.f*(qx*qx + qz*qz), r12 = 2.f*(qy*qz - qr*qx);
    float r20 = 2.f*(qx*qz - qr*qy), r21 = 2.f*(qy*qz + qr*qx), r22 = 1.f - 2.f*(qx*qx + qy*qy);

    float sx2 = sx*sx, sy2 = sy*sy, sz2 = sz*sz;
    // cov = R diag(s^2) R^T (symmetric)
    float c00 = r00*r00*sx2 + r01*r01*sy2 + r02*r02*sz2;
    float c01 = r00*r10*sx2 + r01*r11*sy2 + r02*r12*sz2;
    float c02 = r00*r20*sx2 + r01*r21*sy2 + r02*r22*sz2;
    float c11 = r10*r10*sx2 + r11*r11*sy2 + r12*r12*sz2;
    float c12 = r10*r20*sx2 + r11*r21*sy2 + r12*r22*sz2;
    float c22 = r20*r20*sx2 + r21*r21*sy2 + r22*r22*sz2;

    float sdx = sqrtf(c00), sdy = sqrtf(c11), sdz = sqrtf(c22);
    float bminx = mx - 3.f*sdx, bminy = my - 3.f*sdy, bminz = mz - 3.f*sdz;
    float bmaxx = mx + 3.f*sdx, bmaxy = my + 3.f*sdy, bmaxz = mz + 3.f*sdz;

    // keep mask (filter_gaussians): bbox overlaps volume, opacity above threshold
    bool keep = (bmaxx > -40.f) && (bmaxy > -40.f) && (bmaxz > -4.f)
             && (bminx <  40.f) && (bminy <  40.f) && (bminz <  4.f)
             && (op > 1e-4f);
    if (!keep) return;

    // 3x3 symmetric inverse via adjugate
    float m00 = c11*c22 - c12*c12;
    float m01 = c02*c12 - c01*c22;
    float m02 = c01*c12 - c02*c11;
    float det = c00*m00 + c01*m01 + c02*m02;
    float idet = 1.0f / det;
    float i00 = m00 * idet;
    float i01 = m01 * idet;
    float i02 = m02 * idet;
    float i11 = (c00*c22 - c02*c02) * idet;
    float i12 = (c01*c02 - c00*c12) * idet;
    float i22 = (c00*c11 - c01*c01) * idet;

    // voxel index bounds; IEEE division + trunc-toward-zero matches jnp .astype(int32)
    int ixmin = max((int)__fdiv_rn(bminx + 40.f, 0.4f), 0);
    int iymin = max((int)__fdiv_rn(bminy + 40.f, 0.4f), 0);
    int izmin = max((int)__fdiv_rn(bminz +  4.f, 0.4f), 0);
    int ixmax = min((int)__fdiv_rn(bmaxx + 40.f, 0.4f), GX - 1);
    int iymax = min((int)__fdiv_rn(bmaxy + 40.f, 0.4f), GY - 1);
    int izmax = min((int)__fdiv_rn(bmaxz +  4.f, 0.4f), GZ - 1);

    int cx = min(ixmax - ixmin + 1, 8);
    int cy = min(iymax - iymin + 1, 8);
    int cz = min(izmax - izmin + 1, 8);
    int P = cx * cy * cz;

    // Magic-number reciprocals: exact n/d = (n*m)>>16 for d in [1,8], n <= 512.
    unsigned mcz = (65535u / (unsigned)cz) + 1u;
    unsigned mcy = (65535u / (unsigned)cy) + 1u;

    const float4* fptr = (const float4*)(feats + 8*g);
    float4 f0 = fptr[0];
    float4 f1 = fptr[1];

    for (int p = lane; p < P; p += 32) {
        unsigned t  = ((unsigned)p * mcz) >> 16;   // p / cz
        int oz = p - (int)t * cz;                  // p % cz
        unsigned ox = (t * mcy) >> 16;             // t / cy
        int oy = (int)t - (int)ox * cy;            // t % cy
        int ix = ixmin + (int)ox, iy = iymin + oy, iz = izmin + oz;

        float cxp = ((float)ix * 0.4f + (-40.f)) + 0.2f;
        float cyp = ((float)iy * 0.4f + (-40.f)) + 0.2f;
        float czp = ((float)iz * 0.4f + ( -4.f)) + 0.2f;

        float dx = cxp - mx, dy = cyp - my, dz = czp - mz;
        float maha = i00*dx*dx + i11*dy*dy + i22*dz*dz
                   + 2.f*(i01*dx*dy + i02*dx*dz + i12*dy*dz);
        // exp(-0.5*maha) = exp2(-0.5*log2(e)*maha)
        float w = op * exp2f(-0.72134752f * maha);

        int flat = (ix * GY + iy) * GZ + iz;
        atomicAdd(density + flat, w);
        float* fp = gfeat + (size_t)flat * NCH;
        red_add_v4(fp,     w*f0.x, w*f0.y, w*f0.z, w*f0.w);
        red_add_v4(fp + 4, w*f1.x, w*f1.y, w*f1.z, w*f1.w);
    }
}

// One thread per HALF-voxel (one float4 of channels). Fully coalesced:
// warp reads 32 consecutive float4s of gfeat and 16 consecutive density floats.
__global__ __launch_bounds__(256) void finalize_kernel(const float* __restrict__ density,
                                                        float4* __restrict__ gfeat4) {
    int i = blockIdx.x * blockDim.x + threadIdx.x;
    if (i >= NVOX * 2) return;
    float d = density[i >> 1];
    float4 v = gfeat4[i];
    float inv = 1.0f / fmaxf(d, 1e-6f);
    v.x *= inv; v.y *= inv; v.z *= inv; v.w *= inv;
    gfeat4[i] = v;
}

extern "C" void kernel_launch(void* const* d_in, const int* in_sizes, int n_in,
                              void* d_out, int out_size) {
    const float* means  = (const float*)d_in[0];
    const float* opac   = (const float*)d_in[1];
    const float* scales = (const float*)d_in[2];
    const float* rots   = (const float*)d_in[3];
    const float* feats  = (const float*)d_in[4];

    float* density = (float*)d_out;
    float* gfeat   = density + NVOX;

    int N = in_sizes[1];  // opacities: B*N*1 elements

    zero_kernel<<<1184, 256>>>((float4*)d_out);

    int threads = N * 32;  // one warp per Gaussian
    vox_kernel<<<(threads + 255) / 256, 256>>>(means, opac, scales, rots, feats,
                                               density, gfeat, N);

    int nhalf = NVOX * 2;
    finalize_kernel<<<(nhalf + 255) / 256, 256>>>(density, (float4*)gfeat);
}

// round 11
// speedup vs baseline: 1.5063x; 1.5063x over previous
#include <cuda_runtime.h>
#include <math.h>

#define GX 200
#define GY 200
#define GZ 20
#define NVOX (GX*GY*GZ)               // 800000
#define NCH 8
#define TOTAL_OUT (NVOX * (1 + NCH))  // 7,200,000 floats

// Vector float4 reduction to global memory (sm_90+ PTX).
__device__ __forceinline__ void red_add_v4(float* addr, float a, float b, float c, float d) {
    asm volatile("red.global.add.v4.f32 [%0], {%1,%2,%3,%4};"
                 :: "l"(addr), "f"(a), "f"(b), "f"(c), "f"(d) : "memory");
}

// One warp per Gaussian.
__global__ __launch_bounds__(256) void vox_kernel(
    const float* __restrict__ means, const float* __restrict__ opac,
    const float* __restrict__ scales, const float* __restrict__ rots,
    const float* __restrict__ feats,
    float* __restrict__ density, float* __restrict__ gfeat, int N)
{
    int g    = (blockIdx.x * blockDim.x + threadIdx.x) >> 5;
    int lane = threadIdx.x & 31;
    if (g >= N) return;

    // ---- per-Gaussian setup (redundant across lanes; broadcast loads) ----
    float mx = means[3*g+0], my = means[3*g+1], mz = means[3*g+2];
    float op = opac[g];
    float sx = scales[3*g+0], sy = scales[3*g+1], sz = scales[3*g+2];
    float qr = rots[4*g+0], qx = rots[4*g+1], qy = rots[4*g+2], qz = rots[4*g+3];

    float qn = rsqrtf(qr*qr + qx*qx + qy*qy + qz*qz + 1e-8f);
    qr *= qn; qx *= qn; qy *= qn; qz *= qn;

    float r00 = 1.f - 2.f*(qy*qy + qz*qz), r01 = 2.f*(qx*qy - qr*qz), r02 = 2.f*(qx*qz + qr*qy);
    float r10 = 2.f*(qx*qy + qr*qz), r11 = 1.f - 2.f*(qx*qx + qz*qz), r12 = 2.f*(qy*qz - qr*qx);
    float r20 = 2.f*(qx*qz - qr*qy), r21 = 2.f*(qy*qz + qr*qx), r22 = 1.f - 2.f*(qx*qx + qy*qy);

    float sx2 = sx*sx, sy2 = sy*sy, sz2 = sz*sz;
    // cov = R diag(s^2) R^T (symmetric)
    float c00 = r00*r00*sx2 + r01*r01*sy2 + r02*r02*sz2;
    float c01 = r00*r10*sx2 + r01*r11*sy2 + r02*r12*sz2;
    float c02 = r00*r20*sx2 + r01*r21*sy2 + r02*r22*sz2;
    float c11 = r10*r10*sx2 + r11*r11*sy2 + r12*r12*sz2;
    float c12 = r10*r20*sx2 + r11*r21*sy2 + r12*r22*sz2;
    float c22 = r20*r20*sx2 + r21*r21*sy2 + r22*r22*sz2;

    float sdx = sqrtf(c00), sdy = sqrtf(c11), sdz = sqrtf(c22);
    float bminx = mx - 3.f*sdx, bminy = my - 3.f*sdy, bminz = mz - 3.f*sdz;
    float bmaxx = mx + 3.f*sdx, bmaxy = my + 3.f*sdy, bmaxz = mz + 3.f*sdz;

    // keep mask (filter_gaussians): bbox overlaps volume, opacity above threshold
    bool keep = (bmaxx > -40.f) && (bmaxy > -40.f) && (bmaxz > -4.f)
             && (bminx <  40.f) && (bminy <  40.f) && (bminz <  4.f)
             && (op > 1e-4f);
    if (!keep) return;

    // 3x3 symmetric inverse via adjugate
    float m00 = c11*c22 - c12*c12;
    float m01 = c02*c12 - c01*c22;
    float m02 = c01*c12 - c02*c11;
    float det = c00*m00 + c01*m01 + c02*m02;
    float idet = 1.0f / det;
    float i00 = m00 * idet;
    float i01 = m01 * idet;
    float i02 = m02 * idet;
    float i11 = (c00*c22 - c02*c02) * idet;
    float i12 = (c01*c02 - c00*c12) * idet;
    float i22 = (c00*c11 - c01*c01) * idet;

    // voxel index bounds; IEEE division + trunc-toward-zero matches jnp .astype(int32)
    int ixmin = max((int)__fdiv_rn(bminx + 40.f, 0.4f), 0);
    int iymin = max((int)__fdiv_rn(bminy + 40.f, 0.4f), 0);
    int izmin = max((int)__fdiv_rn(bminz +  4.f, 0.4f), 0);
    int ixmax = min((int)__fdiv_rn(bmaxx + 40.f, 0.4f), GX - 1);
    int iymax = min((int)__fdiv_rn(bmaxy + 40.f, 0.4f), GY - 1);
    int izmax = min((int)__fdiv_rn(bmaxz +  4.f, 0.4f), GZ - 1);

    int cx = min(ixmax - ixmin + 1, 8);
    int cy = min(iymax - iymin + 1, 8);
    int cz = min(izmax - izmin + 1, 8);
    int P = cx * cy * cz;

    // Magic-number reciprocals: exact n/d = (n*m)>>16 for d in [1,8], n <= 512.
    unsigned mcz = (65535u / (unsigned)cz) + 1u;
    unsigned mcy = (65535u / (unsigned)cy) + 1u;

    const float4* fptr = (const float4*)(feats + 8*g);
    float4 f0 = fptr[0];
    float4 f1 = fptr[1];

    for (int p = lane; p < P; p += 32) {
        unsigned t  = ((unsigned)p * mcz) >> 16;   // p / cz
        int oz = p - (int)t * cz;                  // p % cz
        unsigned ox = (t * mcy) >> 16;             // t / cy
        int oy = (int)t - (int)ox * cy;            // t % cy
        int ix = ixmin + (int)ox, iy = iymin + oy, iz = izmin + oz;

        float cxp = ((float)ix * 0.4f + (-40.f)) + 0.2f;
        float cyp = ((float)iy * 0.4f + (-40.f)) + 0.2f;
        float czp = ((float)iz * 0.4f + ( -4.f)) + 0.2f;

        float dx = cxp - mx, dy = cyp - my, dz = czp - mz;
        float maha = i00*dx*dx + i11*dy*dy + i22*dz*dz
                   + 2.f*(i01*dx*dy + i02*dx*dz + i12*dy*dz);
        // exp(-0.5*maha) = exp2(-0.5*log2(e)*maha)
        float w = op * exp2f(-0.72134752f * maha);

        int flat = (ix * GY + iy) * GZ + iz;
        atomicAdd(density + flat, w);
        float* fp = gfeat + (size_t)flat * NCH;
        red_add_v4(fp,     w*f0.x, w*f0.y, w*f0.z, w*f0.w);
        red_add_v4(fp + 4, w*f1.x, w*f1.y, w*f1.z, w*f1.w);
    }
}

// One thread per HALF-voxel (one float4 of channels). Fully coalesced:
// warp reads 32 consecutive float4s of gfeat and 16 consecutive density floats.
__global__ __launch_bounds__(256) void finalize_kernel(const float* __restrict__ density,
                                                        float4* __restrict__ gfeat4) {
    int i = blockIdx.x * blockDim.x + threadIdx.x;
    if (i >= NVOX * 2) return;
    float d = density[i >> 1];
    float4 v = gfeat4[i];
    float inv = 1.0f / fmaxf(d, 1e-6f);
    v.x *= inv; v.y *= inv; v.z *= inv; v.w *= inv;
    gfeat4[i] = v;
}

extern "C" void kernel_launch(void* const* d_in, const int* in_sizes, int n_in,
                              void* d_out, int out_size) {
    const float* means  = (const float*)d_in[0];
    const float* opac   = (const float*)d_in[1];
    const float* scales = (const float*)d_in[2];
    const float* rots   = (const float*)d_in[3];
    const float* feats  = (const float*)d_in[4];

    float* density = (float*)d_out;
    float* gfeat   = density + NVOX;

    int N = in_sizes[1];  // opacities: B*N*1 elements

    cudaMemsetAsync(d_out, 0, (size_t)TOTAL_OUT * sizeof(float), 0);

    int threads = N * 32;  // one warp per Gaussian
    vox_kernel<<<(threads + 255) / 256, 256>>>(means, opac, scales, rots, feats,
                                               density, gfeat, N);

    int nhalf = NVOX * 2;
    finalize_kernel<<<(nhalf + 255) / 256, 256>>>(density, (float4*)gfeat);
}